// round 13
// baseline (speedup 1.0000x reference)
#include <cuda_runtime.h>
#include <cuda_fp16.h>

#define NN 100000
#define NE 1600000
#define NB_SCAN ((NN + 1023) / 1024)   // 98

__device__ int   g_cnt[NN];
__device__ int   g_off[NN + 1];
__device__ int   g_bsum[NB_SCAN];
__device__ int   g_fill[NN];
__device__ int   g_srcs[NE];
__device__ float g_dinv[NN];
// Gather tables in fp16 (same 10-bit mantissa as tf32): 12.8 MB each.
__device__ __align__(16) __half g_t[NN * 64];   // raw t = x@W1
__device__ __align__(16) __half g_a[NN * 64];   // hh = dinv*relu(dinv*agg1 + b1)

__device__ __forceinline__ unsigned f2tf(float f) {
    unsigned u;
    asm("cvt.rna.tf32.f32 %0, %1;" : "=r"(u) : "f"(f));
    return u;
}

__device__ __forceinline__ void mma_tf32(float* d, const unsigned* a, unsigned b0, unsigned b1) {
    asm("mma.sync.aligned.m16n8k8.row.col.f32.tf32.tf32.f32 "
        "{%0,%1,%2,%3},{%4,%5,%6,%7},{%8,%9},{%0,%1,%2,%3};"
        : "+f"(d[0]), "+f"(d[1]), "+f"(d[2]), "+f"(d[3])
        : "r"(a[0]), "r"(a[1]), "r"(a[2]), "r"(a[3]), "r"(b0), "r"(b1));
}

// Accumulate 8 halves (one uint4) into 8 floats with weight w.
__device__ __forceinline__ void acc8(float* acc, uint4 u, float w) {
    float2 f0 = __half22float2(*(const __half2*)&u.x);
    float2 f1 = __half22float2(*(const __half2*)&u.y);
    float2 f2 = __half22float2(*(const __half2*)&u.z);
    float2 f3 = __half22float2(*(const __half2*)&u.w);
    acc[0] += w * f0.x; acc[1] += w * f0.y;
    acc[2] += w * f1.x; acc[3] += w * f1.y;
    acc[4] += w * f2.x; acc[5] += w * f2.y;
    acc[6] += w * f3.x; acc[7] += w * f3.y;
}

// Unweighted add of 8 halves.
__device__ __forceinline__ void add8(float* acc, uint4 u) {
    float2 f0 = __half22float2(*(const __half2*)&u.x);
    float2 f1 = __half22float2(*(const __half2*)&u.y);
    float2 f2 = __half22float2(*(const __half2*)&u.z);
    float2 f3 = __half22float2(*(const __half2*)&u.w);
    acc[0] += f0.x; acc[1] += f0.y;
    acc[2] += f1.x; acc[3] += f1.y;
    acc[4] += f2.x; acc[5] += f2.y;
    acc[6] += f3.x; acc[7] += f3.y;
}

__global__ void k_zero() {
    int i = blockIdx.x * 256 + threadIdx.x;
    if (i < NN) g_cnt[i] = 0;
}

// 4 edges/thread via int4.
__global__ void k_count(const int* __restrict__ dst) {
    int i = blockIdx.x * 256 + threadIdx.x;
    if (i < NE / 4) {
        int4 d4 = ((const int4*)dst)[i];
        atomicAdd(&g_cnt[d4.x], 1);
        atomicAdd(&g_cnt[d4.y], 1);
        atomicAdd(&g_cnt[d4.z], 1);
        atomicAdd(&g_cnt[d4.w], 1);
    }
}

// Block-local exclusive scan; block totals to g_bsum.
__global__ __launch_bounds__(256) void k_scan1() {
    __shared__ int sh[256];
    int b = blockIdx.x, t = threadIdx.x;
    int base = b * 1024 + t * 4;
    int c0 = (base + 0 < NN) ? g_cnt[base + 0] : 0;
    int c1 = (base + 1 < NN) ? g_cnt[base + 1] : 0;
    int c2 = (base + 2 < NN) ? g_cnt[base + 2] : 0;
    int c3 = (base + 3 < NN) ? g_cnt[base + 3] : 0;
    int s = c0 + c1 + c2 + c3;
    sh[t] = s;
    __syncthreads();
    for (int ofs = 1; ofs < 256; ofs <<= 1) {
        int v = (t >= ofs) ? sh[t - ofs] : 0;
        __syncthreads();
        sh[t] += v;
        __syncthreads();
    }
    int excl = sh[t] - s;
    if (base + 0 < NN) g_off[base + 0] = excl;
    if (base + 1 < NN) g_off[base + 1] = excl + c0;
    if (base + 2 < NN) g_off[base + 2] = excl + c0 + c1;
    if (base + 3 < NN) g_off[base + 3] = excl + c0 + c1 + c2;
    if (t == 255) g_bsum[b] = sh[255];
}

// Finalize offsets (each block re-scans the 98 bsums itself), init fill
// cursors, compute dinv.
__global__ __launch_bounds__(256) void k_scan3() {
    __shared__ int sh[128];
    __shared__ int ex[128];
    int t = threadIdx.x;
    if (t < 128) sh[t] = (t < NB_SCAN) ? g_bsum[t] : 0;
    __syncthreads();
    int orig = (t < 128) ? sh[t] : 0;
    #pragma unroll
    for (int ofs = 1; ofs < 128; ofs <<= 1) {
        int u = (t < 128 && t >= ofs) ? sh[t - ofs] : 0;
        __syncthreads();
        if (t < 128) sh[t] += u;
        __syncthreads();
    }
    if (t < 128) ex[t] = sh[t] - orig;
    __syncthreads();

    int i = blockIdx.x * 256 + t;
    if (i < NN) {
        int o = g_off[i] + ex[i >> 10];
        g_off[i] = o;
        g_fill[i] = o;
        g_dinv[i] = rsqrtf((float)(g_cnt[i] + 1));
    }
    if (blockIdx.x == 0 && t == 0) g_off[NN] = NE;
}

// 4 edges/thread via int4.
__global__ void k_fillcsr(const int* __restrict__ src, const int* __restrict__ dst) {
    int i = blockIdx.x * 256 + threadIdx.x;
    if (i < NE / 4) {
        int4 s4 = ((const int4*)src)[i];
        int4 d4 = ((const int4*)dst)[i];
        g_srcs[atomicAdd(&g_fill[d4.x], 1)] = s4.x;
        g_srcs[atomicAdd(&g_fill[d4.y], 1)] = s4.y;
        g_srcs[atomicAdd(&g_fill[d4.z], 1)] = s4.z;
        g_srcs[atomicAdd(&g_fill[d4.w], 1)] = s4.w;
    }
}

// RAW t = x[N,128] @ W1[128,64] via tf32 mma; result stored fp16.
__global__ __launch_bounds__(256) void k_gemm1(const float* __restrict__ x,
                                               const float* __restrict__ W) {
    __shared__ unsigned xs[128 * 132];
    __shared__ unsigned ws[128 * 72];
    int tid = threadIdx.x;
    int row0 = blockIdx.x * 128;
    const float4* x4 = (const float4*)x;
    const float4* W4 = (const float4*)W;

    #pragma unroll
    for (int i = tid; i < 2048; i += 256) {
        int k = i >> 4, q = i & 15;
        float4 v = W4[i];
        unsigned* p = &ws[k * 72 + q * 4];
        p[0] = f2tf(v.x); p[1] = f2tf(v.y); p[2] = f2tf(v.z); p[3] = f2tf(v.w);
    }
    #pragma unroll
    for (int i = tid; i < 4096; i += 256) {
        int r = i >> 5, q = i & 31;
        int gr = row0 + r;
        float4 v = (gr < NN) ? x4[gr * 32 + q] : make_float4(0, 0, 0, 0);
        unsigned* p = &xs[r * 132 + q * 4];
        p[0] = f2tf(v.x); p[1] = f2tf(v.y); p[2] = f2tf(v.z); p[3] = f2tf(v.w);
    }
    __syncthreads();

    int warp = tid >> 5, lane = tid & 31;
    int gid = lane >> 2, tig = lane & 3;
    int wr = warp * 16;
    float acc[8][4];
    #pragma unroll
    for (int nt = 0; nt < 8; nt++)
        #pragma unroll
        for (int j = 0; j < 4; j++) acc[nt][j] = 0.f;

    #pragma unroll 4
    for (int ks = 0; ks < 16; ks++) {
        int k0 = ks * 8;
        unsigned a[4];
        a[0] = xs[(wr + gid) * 132 + k0 + tig];
        a[1] = xs[(wr + gid + 8) * 132 + k0 + tig];
        a[2] = xs[(wr + gid) * 132 + k0 + tig + 4];
        a[3] = xs[(wr + gid + 8) * 132 + k0 + tig + 4];
        #pragma unroll
        for (int nt = 0; nt < 8; nt++) {
            unsigned b0 = ws[(k0 + tig) * 72 + nt * 8 + gid];
            unsigned b1 = ws[(k0 + tig + 4) * 72 + nt * 8 + gid];
            mma_tf32(acc[nt], a, b0, b1);
        }
    }

    int r0 = row0 + wr + gid;
    int r1 = r0 + 8;
    __half2* t2 = (__half2*)g_t;
    #pragma unroll
    for (int nt = 0; nt < 8; nt++) {
        int c2i = nt * 4 + tig;
        if (r0 < NN) t2[r0 * 32 + c2i] = __floats2half2_rn(acc[nt][0], acc[nt][1]);
        if (r1 < NN) t2[r1 * 32 + c2i] = __floats2half2_rn(acc[nt][2], acc[nt][3]);
    }
}

// Layer-1 CSR gather-reduce: reads raw g_t weighted by dinv[s], writes
// g_a = dinv*relu(dinv*acc + b1). 8 threads/node x uint4; 4-way MLP.
__global__ __launch_bounds__(256) void k_aggcsr1(const float* __restrict__ b1) {
    int idx = blockIdx.x * 256 + threadIdx.x;
    int d = idx >> 3;
    if (d >= NN) return;
    int sub = idx & 7;
    const uint4* t16 = (const uint4*)g_t;
    int beg = g_off[d], end = g_off[d + 1];
    float s = g_dinv[d];

    float acc[8];
    #pragma unroll
    for (int i = 0; i < 8; i++) acc[i] = 0.f;
    acc8(acc, t16[d * 8 + sub], s);   // self-loop term

    int j = beg;
    for (; j + 3 < end; j += 4) {
        int s0 = g_srcs[j + 0];
        int s1 = g_srcs[j + 1];
        int s2 = g_srcs[j + 2];
        int s3 = g_srcs[j + 3];
        uint4 u0 = t16[s0 * 8 + sub];
        uint4 u1 = t16[s1 * 8 + sub];
        uint4 u2 = t16[s2 * 8 + sub];
        uint4 u3 = t16[s3 * 8 + sub];
        acc8(acc, u0, g_dinv[s0]);
        acc8(acc, u1, g_dinv[s1]);
        acc8(acc, u2, g_dinv[s2]);
        acc8(acc, u3, g_dinv[s3]);
    }
    for (; j < end; j++) {
        int s0 = g_srcs[j];
        acc8(acc, t16[s0 * 8 + sub], g_dinv[s0]);
    }

    const float4* b4 = (const float4*)b1;
    float4 ba = b4[sub * 2], bb = b4[sub * 2 + 1];
    float b[8] = {ba.x, ba.y, ba.z, ba.w, bb.x, bb.y, bb.z, bb.w};
    #pragma unroll
    for (int i = 0; i < 8; i++) acc[i] = fmaxf(s * acc[i] + b[i], 0.f) * s;
    uint4 o;
    *(__half2*)&o.x = __floats2half2_rn(acc[0], acc[1]);
    *(__half2*)&o.y = __floats2half2_rn(acc[2], acc[3]);
    *(__half2*)&o.z = __floats2half2_rn(acc[4], acc[5]);
    *(__half2*)&o.w = __floats2half2_rn(acc[6], acc[7]);
    ((uint4*)g_a)[d * 8 + sub] = o;
}

// FUSED layer-2: aggregate g_a rows directly into the tf32 smem tile
// (2 threads/row x 32 cols, 4 uint4/edge, 2-way unroll), then tf32 mma with W2.
// out = dinv*(agg2) @ W2 + b2.
__global__ __launch_bounds__(256) void k_agg2gemm2(const float* __restrict__ W2,
                                                   const float* __restrict__ b2,
                                                   float* __restrict__ out) {
    __shared__ unsigned xs[128 * 68];
    __shared__ unsigned ws[64 * 136];
    int tid = threadIdx.x;
    int row0 = blockIdx.x * 128;
    const float4* W4 = (const float4*)W2;

    #pragma unroll
    for (int i = tid; i < 2048; i += 256) {
        int k = i >> 5, q = i & 31;
        float4 v = W4[i];
        unsigned* p = &ws[k * 136 + q * 4];
        p[0] = f2tf(v.x); p[1] = f2tf(v.y); p[2] = f2tf(v.z); p[3] = f2tf(v.w);
    }

    // Phase A: aggregation into registers, then tf32 into xs.
    {
        int r = tid >> 1, half = tid & 1;
        int gr = row0 + r;
        float acc[32];
        #pragma unroll
        for (int i = 0; i < 32; i++) acc[i] = 0.f;
        if (gr < NN) {
            const uint4* t16 = (const uint4*)g_a + half * 4;
            {   // self-loop term
                const uint4* rp = t16 + gr * 8;
                add8(acc + 0, rp[0]); add8(acc + 8, rp[1]);
                add8(acc + 16, rp[2]); add8(acc + 24, rp[3]);
            }
            int beg = g_off[gr], end = g_off[gr + 1];
            int j = beg;
            for (; j + 1 < end; j += 2) {
                int s0 = g_srcs[j];
                int s1 = g_srcs[j + 1];
                const uint4* p0 = t16 + s0 * 8;
                const uint4* p1 = t16 + s1 * 8;
                uint4 a0 = p0[0], a1 = p0[1], a2 = p0[2], a3 = p0[3];
                uint4 c0 = p1[0], c1 = p1[1], c2 = p1[2], c3 = p1[3];
                add8(acc + 0, a0); add8(acc + 8, a1);
                add8(acc + 16, a2); add8(acc + 24, a3);
                add8(acc + 0, c0); add8(acc + 8, c1);
                add8(acc + 16, c2); add8(acc + 24, c3);
            }
            if (j < end) {
                const uint4* p0 = t16 + g_srcs[j] * 8;
                add8(acc + 0, p0[0]); add8(acc + 8, p0[1]);
                add8(acc + 16, p0[2]); add8(acc + 24, p0[3]);
            }
            float s = g_dinv[gr];
            #pragma unroll
            for (int i = 0; i < 32; i++) acc[i] *= s;
        }
        unsigned* p = &xs[r * 68 + half * 32];
        #pragma unroll
        for (int i = 0; i < 32; i++) p[i] = f2tf(acc[i]);
    }
    __syncthreads();

    // Phase B: tf32 mma (as before).
    int warp = tid >> 5, lane = tid & 31;
    int gid = lane >> 2, tig = lane & 3;
    int wr = warp * 16;
    float acc[16][4];
    #pragma unroll
    for (int nt = 0; nt < 16; nt++)
        #pragma unroll
        for (int j = 0; j < 4; j++) acc[nt][j] = 0.f;

    #pragma unroll 2
    for (int ks = 0; ks < 8; ks++) {
        int k0 = ks * 8;
        unsigned a[4];
        a[0] = xs[(wr + gid) * 68 + k0 + tig];
        a[1] = xs[(wr + gid + 8) * 68 + k0 + tig];
        a[2] = xs[(wr + gid) * 68 + k0 + tig + 4];
        a[3] = xs[(wr + gid + 8) * 68 + k0 + tig + 4];
        #pragma unroll
        for (int nt = 0; nt < 16; nt++) {
            unsigned b0 = ws[(k0 + tig) * 136 + nt * 8 + gid];
            unsigned b1 = ws[(k0 + tig + 4) * 136 + nt * 8 + gid];
            mma_tf32(acc[nt], a, b0, b1);
        }
    }

    int r0 = row0 + wr + gid;
    int r1 = r0 + 8;
    float2* o2 = (float2*)out;
    #pragma unroll
    for (int nt = 0; nt < 16; nt++) {
        int col = nt * 8 + 2 * tig;
        float bx = __ldg(&b2[col]), by = __ldg(&b2[col + 1]);
        int c2i = col >> 1;
        if (r0 < NN) o2[r0 * 64 + c2i] = make_float2(acc[nt][0] + bx, acc[nt][1] + by);
        if (r1 < NN) o2[r1 * 64 + c2i] = make_float2(acc[nt][2] + bx, acc[nt][3] + by);
    }
}

extern "C" void kernel_launch(void* const* d_in, const int* in_sizes, int n_in,
                              void* d_out, int out_size) {
    const float* x  = (const float*)d_in[0];
    const int*   ei = (const int*)d_in[1];   // [2, E] int32
    const float* W1 = (const float*)d_in[2];
    const float* b1 = (const float*)d_in[3];
    const float* W2 = (const float*)d_in[4];
    const float* b2 = (const float*)d_in[5];
    float* out = (float*)d_out;

    const int* src = ei;
    const int* dst = ei + NE;

    static cudaStream_t s2 = nullptr;
    static cudaEvent_t e_fork = nullptr, e_join = nullptr;
    if (!s2) {
        cudaStreamCreateWithFlags(&s2, cudaStreamNonBlocking);
        cudaEventCreateWithFlags(&e_fork, cudaEventDisableTiming);
        cudaEventCreateWithFlags(&e_join, cudaEventDisableTiming);
    }

    // Fork: gemm1 runs parallel to CSR build.
    cudaEventRecord(e_fork, 0);
    cudaStreamWaitEvent(s2, e_fork, 0);
    k_gemm1<<<(NN + 127) / 128, 256, 0, s2>>>(x, W1);
    cudaEventRecord(e_join, s2);

    // CSR build on the main (capture) stream.
    k_zero   <<<(NN + 255) / 256, 256>>>();
    k_count  <<<(NE / 4 + 255) / 256, 256>>>(dst);
    k_scan1  <<<NB_SCAN, 256>>>();
    k_scan3  <<<(NN + 255) / 256, 256>>>();
    k_fillcsr<<<(NE / 4 + 255) / 256, 256>>>(src, dst);

    cudaStreamWaitEvent(0, e_join, 0);
    k_aggcsr1  <<<(NN * 8 + 255) / 256, 256>>>(b1);
    k_agg2gemm2<<<(NN + 127) / 128, 256>>>(W2, b2, out);
}

// round 15
// speedup vs baseline: 1.0800x; 1.0800x over previous
#include <cuda_runtime.h>
#include <cuda_fp16.h>

#define NN 100000
#define NE 1600000
#define NB_SCAN ((NN + 1023) / 1024)   // 98

__device__ int   g_cnt[NN];
__device__ int   g_off[NN + 1];
__device__ int   g_bsum[NB_SCAN];
__device__ int   g_fill[NN];
__device__ int   g_srcs[NE];
__device__ float g_dinv[NN];
// Gather tables in fp16 (same 10-bit mantissa as tf32): 12.8 MB each.
__device__ __align__(16) __half g_t[NN * 64];   // raw t = x@W1; later dinv*agg2 (gemm2 input)
__device__ __align__(16) __half g_a[NN * 64];   // hh = dinv*relu(dinv*agg1 + b1)

__device__ __forceinline__ unsigned f2tf(float f) {
    unsigned u;
    asm("cvt.rna.tf32.f32 %0, %1;" : "=r"(u) : "f"(f));
    return u;
}

__device__ __forceinline__ void mma_tf32(float* d, const unsigned* a, unsigned b0, unsigned b1) {
    asm("mma.sync.aligned.m16n8k8.row.col.f32.tf32.tf32.f32 "
        "{%0,%1,%2,%3},{%4,%5,%6,%7},{%8,%9},{%0,%1,%2,%3};"
        : "+f"(d[0]), "+f"(d[1]), "+f"(d[2]), "+f"(d[3])
        : "r"(a[0]), "r"(a[1]), "r"(a[2]), "r"(a[3]), "r"(b0), "r"(b1));
}

// Accumulate 8 halves (one uint4) into 8 floats with weight w.
__device__ __forceinline__ void acc8(float* acc, uint4 u, float w) {
    float2 f0 = __half22float2(*(const __half2*)&u.x);
    float2 f1 = __half22float2(*(const __half2*)&u.y);
    float2 f2 = __half22float2(*(const __half2*)&u.z);
    float2 f3 = __half22float2(*(const __half2*)&u.w);
    acc[0] += w * f0.x; acc[1] += w * f0.y;
    acc[2] += w * f1.x; acc[3] += w * f1.y;
    acc[4] += w * f2.x; acc[5] += w * f2.y;
    acc[6] += w * f3.x; acc[7] += w * f3.y;
}

__global__ void k_zero() {
    int i = blockIdx.x * 256 + threadIdx.x;
    if (i < NN) g_cnt[i] = 0;
}

// 4 edges/thread via int4.
__global__ void k_count(const int* __restrict__ dst) {
    int i = blockIdx.x * 256 + threadIdx.x;
    if (i < NE / 4) {
        int4 d4 = ((const int4*)dst)[i];
        atomicAdd(&g_cnt[d4.x], 1);
        atomicAdd(&g_cnt[d4.y], 1);
        atomicAdd(&g_cnt[d4.z], 1);
        atomicAdd(&g_cnt[d4.w], 1);
    }
}

// Block-local exclusive scan; block totals to g_bsum.
__global__ __launch_bounds__(256) void k_scan1() {
    __shared__ int sh[256];
    int b = blockIdx.x, t = threadIdx.x;
    int base = b * 1024 + t * 4;
    int c0 = (base + 0 < NN) ? g_cnt[base + 0] : 0;
    int c1 = (base + 1 < NN) ? g_cnt[base + 1] : 0;
    int c2 = (base + 2 < NN) ? g_cnt[base + 2] : 0;
    int c3 = (base + 3 < NN) ? g_cnt[base + 3] : 0;
    int s = c0 + c1 + c2 + c3;
    sh[t] = s;
    __syncthreads();
    for (int ofs = 1; ofs < 256; ofs <<= 1) {
        int v = (t >= ofs) ? sh[t - ofs] : 0;
        __syncthreads();
        sh[t] += v;
        __syncthreads();
    }
    int excl = sh[t] - s;
    if (base + 0 < NN) g_off[base + 0] = excl;
    if (base + 1 < NN) g_off[base + 1] = excl + c0;
    if (base + 2 < NN) g_off[base + 2] = excl + c0 + c1;
    if (base + 3 < NN) g_off[base + 3] = excl + c0 + c1 + c2;
    if (t == 255) g_bsum[b] = sh[255];
}

// Finalize offsets (each block re-scans the 98 bsums itself), init fill
// cursors, compute dinv.
__global__ __launch_bounds__(256) void k_scan3() {
    __shared__ int sh[128];
    __shared__ int ex[128];
    int t = threadIdx.x;
    if (t < 128) sh[t] = (t < NB_SCAN) ? g_bsum[t] : 0;
    __syncthreads();
    int orig = (t < 128) ? sh[t] : 0;
    #pragma unroll
    for (int ofs = 1; ofs < 128; ofs <<= 1) {
        int u = (t < 128 && t >= ofs) ? sh[t - ofs] : 0;
        __syncthreads();
        if (t < 128) sh[t] += u;
        __syncthreads();
    }
    if (t < 128) ex[t] = sh[t] - orig;
    __syncthreads();

    int i = blockIdx.x * 256 + t;
    if (i < NN) {
        int o = g_off[i] + ex[i >> 10];
        g_off[i] = o;
        g_fill[i] = o;
        g_dinv[i] = rsqrtf((float)(g_cnt[i] + 1));
    }
    if (blockIdx.x == 0 && t == 0) g_off[NN] = NE;
}

// 4 edges/thread via int4.
__global__ void k_fillcsr(const int* __restrict__ src, const int* __restrict__ dst) {
    int i = blockIdx.x * 256 + threadIdx.x;
    if (i < NE / 4) {
        int4 s4 = ((const int4*)src)[i];
        int4 d4 = ((const int4*)dst)[i];
        g_srcs[atomicAdd(&g_fill[d4.x], 1)] = s4.x;
        g_srcs[atomicAdd(&g_fill[d4.y], 1)] = s4.y;
        g_srcs[atomicAdd(&g_fill[d4.z], 1)] = s4.z;
        g_srcs[atomicAdd(&g_fill[d4.w], 1)] = s4.w;
    }
}

// RAW t = x[N,128] @ W1[128,64] via tf32 mma; result stored fp16.
__global__ __launch_bounds__(256) void k_gemm1(const float* __restrict__ x,
                                               const float* __restrict__ W) {
    __shared__ unsigned xs[128 * 132];
    __shared__ unsigned ws[128 * 72];
    int tid = threadIdx.x;
    int row0 = blockIdx.x * 128;
    const float4* x4 = (const float4*)x;
    const float4* W4 = (const float4*)W;

    #pragma unroll
    for (int i = tid; i < 2048; i += 256) {
        int k = i >> 4, q = i & 15;
        float4 v = W4[i];
        unsigned* p = &ws[k * 72 + q * 4];
        p[0] = f2tf(v.x); p[1] = f2tf(v.y); p[2] = f2tf(v.z); p[3] = f2tf(v.w);
    }
    #pragma unroll
    for (int i = tid; i < 4096; i += 256) {
        int r = i >> 5, q = i & 31;
        int gr = row0 + r;
        float4 v = (gr < NN) ? x4[gr * 32 + q] : make_float4(0, 0, 0, 0);
        unsigned* p = &xs[r * 132 + q * 4];
        p[0] = f2tf(v.x); p[1] = f2tf(v.y); p[2] = f2tf(v.z); p[3] = f2tf(v.w);
    }
    __syncthreads();

    int warp = tid >> 5, lane = tid & 31;
    int gid = lane >> 2, tig = lane & 3;
    int wr = warp * 16;
    float acc[8][4];
    #pragma unroll
    for (int nt = 0; nt < 8; nt++)
        #pragma unroll
        for (int j = 0; j < 4; j++) acc[nt][j] = 0.f;

    #pragma unroll 4
    for (int ks = 0; ks < 16; ks++) {
        int k0 = ks * 8;
        unsigned a[4];
        a[0] = xs[(wr + gid) * 132 + k0 + tig];
        a[1] = xs[(wr + gid + 8) * 132 + k0 + tig];
        a[2] = xs[(wr + gid) * 132 + k0 + tig + 4];
        a[3] = xs[(wr + gid + 8) * 132 + k0 + tig + 4];
        #pragma unroll
        for (int nt = 0; nt < 8; nt++) {
            unsigned b0 = ws[(k0 + tig) * 72 + nt * 8 + gid];
            unsigned b1 = ws[(k0 + tig + 4) * 72 + nt * 8 + gid];
            mma_tf32(acc[nt], a, b0, b1);
        }
    }

    int r0 = row0 + wr + gid;
    int r1 = r0 + 8;
    __half2* t2 = (__half2*)g_t;
    #pragma unroll
    for (int nt = 0; nt < 8; nt++) {
        int c2i = nt * 4 + tig;
        if (r0 < NN) t2[r0 * 32 + c2i] = __floats2half2_rn(acc[nt][0], acc[nt][1]);
        if (r1 < NN) t2[r1 * 32 + c2i] = __floats2half2_rn(acc[nt][2], acc[nt][3]);
    }
}

// CSR gather-reduce over fp16 rows, fp32 accumulate, no atomics.
// 8 threads/node x uint4 (16B = 8 halves) each; 4-way unrolled gather (MLP=4).
// LAYER 1: reads raw g_t, weights rows by dinv[s]; writes g_a = dinv*relu(dinv*acc+b1).
// LAYER 2: reads pre-scaled g_a; writes g_t = dinv*acc.
template <int LAYER>
__global__ __launch_bounds__(256) void k_aggcsr(const float* __restrict__ b1) {
    int idx = blockIdx.x * 256 + threadIdx.x;
    int d = idx >> 3;
    if (d >= NN) return;
    int sub = idx & 7;                        // 8 threads/node
    const uint4* t16 = (const uint4*)(LAYER == 1 ? g_t : g_a);   // row = 8 uint4
    int beg = g_off[d], end = g_off[d + 1];
    float s = g_dinv[d];

    float acc[8];
    #pragma unroll
    for (int i = 0; i < 8; i++) acc[i] = 0.f;
    acc8(acc, t16[d * 8 + sub], (LAYER == 1) ? s : 1.f);   // self-loop term

    int j = beg;
    for (; j + 3 < end; j += 4) {
        int s0 = g_srcs[j + 0];
        int s1 = g_srcs[j + 1];
        int s2 = g_srcs[j + 2];
        int s3 = g_srcs[j + 3];
        uint4 u0 = t16[s0 * 8 + sub];
        uint4 u1 = t16[s1 * 8 + sub];
        uint4 u2 = t16[s2 * 8 + sub];
        uint4 u3 = t16[s3 * 8 + sub];
        if (LAYER == 1) {
            acc8(acc, u0, g_dinv[s0]);
            acc8(acc, u1, g_dinv[s1]);
            acc8(acc, u2, g_dinv[s2]);
            acc8(acc, u3, g_dinv[s3]);
        } else {
            acc8(acc, u0, 1.f);
            acc8(acc, u1, 1.f);
            acc8(acc, u2, 1.f);
            acc8(acc, u3, 1.f);
        }
    }
    for (; j < end; j++) {
        int s0 = g_srcs[j];
        uint4 u0 = t16[s0 * 8 + sub];
        acc8(acc, u0, (LAYER == 1) ? g_dinv[s0] : 1.f);
    }

    uint4 o;
    if (LAYER == 1) {
        const float4* b4 = (const float4*)b1;
        float4 ba = b4[sub * 2], bb = b4[sub * 2 + 1];
        float b[8] = {ba.x, ba.y, ba.z, ba.w, bb.x, bb.y, bb.z, bb.w};
        #pragma unroll
        for (int i = 0; i < 8; i++) acc[i] = fmaxf(s * acc[i] + b[i], 0.f) * s;
        *(__half2*)&o.x = __floats2half2_rn(acc[0], acc[1]);
        *(__half2*)&o.y = __floats2half2_rn(acc[2], acc[3]);
        *(__half2*)&o.z = __floats2half2_rn(acc[4], acc[5]);
        *(__half2*)&o.w = __floats2half2_rn(acc[6], acc[7]);
        ((uint4*)g_a)[d * 8 + sub] = o;
    } else {
        #pragma unroll
        for (int i = 0; i < 8; i++) acc[i] *= s;
        *(__half2*)&o.x = __floats2half2_rn(acc[0], acc[1]);
        *(__half2*)&o.y = __floats2half2_rn(acc[2], acc[3]);
        *(__half2*)&o.z = __floats2half2_rn(acc[4], acc[5]);
        *(__half2*)&o.w = __floats2half2_rn(acc[6], acc[7]);
        ((uint4*)g_t)[d * 8 + sub] = o;
    }
}

// out = g_t[N,64](fp16, already dinv-scaled) @ W2[64,128] + b2 via tf32 mma.
__global__ __launch_bounds__(256) void k_gemm2(const float* __restrict__ W2,
                                               const float* __restrict__ b2,
                                               float* __restrict__ out) {
    __shared__ unsigned xs[128 * 68];
    __shared__ unsigned ws[64 * 136];
    int tid = threadIdx.x;
    int row0 = blockIdx.x * 128;
    const uint2* a8 = (const uint2*)g_t;
    const float4* W4 = (const float4*)W2;

    #pragma unroll
    for (int i = tid; i < 2048; i += 256) {
        int k = i >> 5, q = i & 31;
        float4 v = W4[i];
        unsigned* p = &ws[k * 136 + q * 4];
        p[0] = f2tf(v.x); p[1] = f2tf(v.y); p[2] = f2tf(v.z); p[3] = f2tf(v.w);
    }
    #pragma unroll
    for (int i = tid; i < 2048; i += 256) {
        int r = i >> 4, q = i & 15;
        int gr = row0 + r;
        float2 f0 = {0, 0}, f1 = {0, 0};
        if (gr < NN) {
            uint2 u = a8[gr * 16 + q];
            f0 = __half22float2(*(const __half2*)&u.x);
            f1 = __half22float2(*(const __half2*)&u.y);
        }
        unsigned* p = &xs[r * 68 + q * 4];
        p[0] = f2tf(f0.x); p[1] = f2tf(f0.y); p[2] = f2tf(f1.x); p[3] = f2tf(f1.y);
    }
    __syncthreads();

    int warp = tid >> 5, lane = tid & 31;
    int gid = lane >> 2, tig = lane & 3;
    int wr = warp * 16;
    float acc[16][4];
    #pragma unroll
    for (int nt = 0; nt < 16; nt++)
        #pragma unroll
        for (int j = 0; j < 4; j++) acc[nt][j] = 0.f;

    #pragma unroll 2
    for (int ks = 0; ks < 8; ks++) {
        int k0 = ks * 8;
        unsigned a[4];
        a[0] = xs[(wr + gid) * 68 + k0 + tig];
        a[1] = xs[(wr + gid + 8) * 68 + k0 + tig];
        a[2] = xs[(wr + gid) * 68 + k0 + tig + 4];
        a[3] = xs[(wr + gid + 8) * 68 + k0 + tig + 4];
        #pragma unroll
        for (int nt = 0; nt < 16; nt++) {
            unsigned b0 = ws[(k0 + tig) * 136 + nt * 8 + gid];
            unsigned b1 = ws[(k0 + tig + 4) * 136 + nt * 8 + gid];
            mma_tf32(acc[nt], a, b0, b1);
        }
    }

    int r0 = row0 + wr + gid;
    int r1 = r0 + 8;
    float2* o2 = (float2*)out;
    #pragma unroll
    for (int nt = 0; nt < 16; nt++) {
        int col = nt * 8 + 2 * tig;
        float bx = __ldg(&b2[col]), by = __ldg(&b2[col + 1]);
        int c2i = col >> 1;
        if (r0 < NN) o2[r0 * 64 + c2i] = make_float2(acc[nt][0] + bx, acc[nt][1] + by);
        if (r1 < NN) o2[r1 * 64 + c2i] = make_float2(acc[nt][2] + bx, acc[nt][3] + by);
    }
}

extern "C" void kernel_launch(void* const* d_in, const int* in_sizes, int n_in,
                              void* d_out, int out_size) {
    const float* x  = (const float*)d_in[0];
    const int*   ei = (const int*)d_in[1];   // [2, E] int32
    const float* W1 = (const float*)d_in[2];
    const float* b1 = (const float*)d_in[3];
    const float* W2 = (const float*)d_in[4];
    const float* b2 = (const float*)d_in[5];
    float* out = (float*)d_out;

    const int* src = ei;
    const int* dst = ei + NE;

    static cudaStream_t s2 = nullptr;
    static cudaEvent_t e_fork = nullptr, e_join = nullptr;
    if (!s2) {
        cudaStreamCreateWithFlags(&s2, cudaStreamNonBlocking);
        cudaEventCreateWithFlags(&e_fork, cudaEventDisableTiming);
        cudaEventCreateWithFlags(&e_join, cudaEventDisableTiming);
    }

    // Fork: gemm1 runs parallel to CSR build.
    cudaEventRecord(e_fork, 0);
    cudaStreamWaitEvent(s2, e_fork, 0);
    k_gemm1<<<(NN + 127) / 128, 256, 0, s2>>>(x, W1);
    cudaEventRecord(e_join, s2);

    // CSR build on the main (capture) stream.
    k_zero   <<<(NN + 255) / 256, 256>>>();
    k_count  <<<(NE / 4 + 255) / 256, 256>>>(dst);
    k_scan1  <<<NB_SCAN, 256>>>();
    k_scan3  <<<(NN + 255) / 256, 256>>>();
    k_fillcsr<<<(NE / 4 + 255) / 256, 256>>>(src, dst);

    cudaStreamWaitEvent(0, e_join, 0);
    k_aggcsr<1><<<(NN * 8 + 255) / 256, 256>>>(b1);
    k_aggcsr<2><<<(NN * 8 + 255) / 256, 256>>>(b1);
    k_gemm2    <<<(NN + 127) / 128, 256>>>(W2, b2, out);
}

// round 17
// speedup vs baseline: 1.0969x; 1.0156x over previous
#include <cuda_runtime.h>
#include <cuda_fp16.h>

#define NN 100000
#define NE 1600000
#define NB_SCAN ((NN + 1023) / 1024)   // 98

__device__ int   g_cnt[NN];            // zero at module load; re-zeroed by k_fillcsr
__device__ int   g_off[NN + 1];
__device__ unsigned long long g_aggpack[NB_SCAN];   // {flag<<63 | block total}; zeroed by k_count
__device__ int   g_fill[NN];
__device__ int   g_srcs[NE];
__device__ float g_dinv[NN];
// Gather tables in fp16 (same 10-bit mantissa as tf32): 12.8 MB each.
__device__ __align__(16) __half g_t[NN * 64];   // raw t = x@W1; later dinv*agg2 (gemm2 input)
__device__ __align__(16) __half g_a[NN * 64];   // hh = dinv*relu(dinv*agg1 + b1)

__device__ __forceinline__ unsigned f2tf(float f) {
    unsigned u;
    asm("cvt.rna.tf32.f32 %0, %1;" : "=r"(u) : "f"(f));
    return u;
}

__device__ __forceinline__ void mma_tf32(float* d, const unsigned* a, unsigned b0, unsigned b1) {
    asm("mma.sync.aligned.m16n8k8.row.col.f32.tf32.tf32.f32 "
        "{%0,%1,%2,%3},{%4,%5,%6,%7},{%8,%9},{%0,%1,%2,%3};"
        : "+f"(d[0]), "+f"(d[1]), "+f"(d[2]), "+f"(d[3])
        : "r"(a[0]), "r"(a[1]), "r"(a[2]), "r"(a[3]), "r"(b0), "r"(b1));
}

// Accumulate 8 halves (one uint4) into 8 floats with weight w.
__device__ __forceinline__ void acc8(float* acc, uint4 u, float w) {
    float2 f0 = __half22float2(*(const __half2*)&u.x);
    float2 f1 = __half22float2(*(const __half2*)&u.y);
    float2 f2 = __half22float2(*(const __half2*)&u.z);
    float2 f3 = __half22float2(*(const __half2*)&u.w);
    acc[0] += w * f0.x; acc[1] += w * f0.y;
    acc[2] += w * f1.x; acc[3] += w * f1.y;
    acc[4] += w * f2.x; acc[5] += w * f2.y;
    acc[6] += w * f3.x; acc[7] += w * f3.y;
}

// 4 edges/thread via int4; also resets the scan flag array for this launch.
__global__ void k_count(const int* __restrict__ dst) {
    int i = blockIdx.x * 256 + threadIdx.x;
    if (i < NB_SCAN) g_aggpack[i] = 0ULL;
    if (i < NE / 4) {
        int4 d4 = ((const int4*)dst)[i];
        atomicAdd(&g_cnt[d4.x], 1);
        atomicAdd(&g_cnt[d4.y], 1);
        atomicAdd(&g_cnt[d4.z], 1);
        atomicAdd(&g_cnt[d4.w], 1);
    }
}

// Single-kernel scan via decoupled lookback (all 98 blocks co-resident on 148
// SMs -> spins always terminate). Also inits fill cursors and computes dinv.
__global__ __launch_bounds__(256) void k_scanall() {
    __shared__ int sh[256];
    __shared__ int pre[256];
    int b = blockIdx.x, t = threadIdx.x;
    int base = b * 1024 + t * 4;
    int c0 = (base + 0 < NN) ? g_cnt[base + 0] : 0;
    int c1 = (base + 1 < NN) ? g_cnt[base + 1] : 0;
    int c2 = (base + 2 < NN) ? g_cnt[base + 2] : 0;
    int c3 = (base + 3 < NN) ? g_cnt[base + 3] : 0;
    int s = c0 + c1 + c2 + c3;
    sh[t] = s;
    __syncthreads();
    for (int ofs = 1; ofs < 256; ofs <<= 1) {
        int v = (t >= ofs) ? sh[t - ofs] : 0;
        __syncthreads();
        sh[t] += v;
        __syncthreads();
    }
    int excl = sh[t] - s;          // block-local exclusive prefix
    int total = sh[255];           // block aggregate

    // Publish aggregate (flag packed in the value -> no separate fence needed).
    if (t == 0)
        atomicExch(&g_aggpack[b], (1ULL << 63) | (unsigned long long)(unsigned)total);

    // Lookback: thread t spins for predecessor t's aggregate (t < b).
    int part = 0;
    if (t < b) {
        volatile unsigned long long* p = &g_aggpack[t];
        unsigned long long v;
        do { v = *p; } while (!(v >> 63));
        part = (int)(unsigned)(v & 0xffffffffULL);
    }
    pre[t] = part;
    __syncthreads();
    #pragma unroll
    for (int ofs = 128; ofs > 0; ofs >>= 1) {
        if (t < ofs) pre[t] += pre[t + ofs];
        __syncthreads();
    }
    int P = pre[0];                // sum of predecessor aggregates

    int o0 = P + excl;
    if (base + 0 < NN) { g_off[base+0] = o0;           g_fill[base+0] = o0;           g_dinv[base+0] = rsqrtf((float)(c0+1)); }
    if (base + 1 < NN) { g_off[base+1] = o0+c0;        g_fill[base+1] = o0+c0;        g_dinv[base+1] = rsqrtf((float)(c1+1)); }
    if (base + 2 < NN) { g_off[base+2] = o0+c0+c1;     g_fill[base+2] = o0+c0+c1;     g_dinv[base+2] = rsqrtf((float)(c2+1)); }
    if (base + 3 < NN) { g_off[base+3] = o0+c0+c1+c2;  g_fill[base+3] = o0+c0+c1+c2;  g_dinv[base+3] = rsqrtf((float)(c3+1)); }
    if (b == 0 && t == 0) g_off[NN] = NE;
}

// 4 edges/thread via int4; also re-zeroes g_cnt (dead after k_scanall) so the
// next launch starts clean — keeps every call's work identical.
__global__ void k_fillcsr(const int* __restrict__ src, const int* __restrict__ dst) {
    int i = blockIdx.x * 256 + threadIdx.x;
    if (i < NN) g_cnt[i] = 0;
    if (i < NE / 4) {
        int4 s4 = ((const int4*)src)[i];
        int4 d4 = ((const int4*)dst)[i];
        g_srcs[atomicAdd(&g_fill[d4.x], 1)] = s4.x;
        g_srcs[atomicAdd(&g_fill[d4.y], 1)] = s4.y;
        g_srcs[atomicAdd(&g_fill[d4.z], 1)] = s4.z;
        g_srcs[atomicAdd(&g_fill[d4.w], 1)] = s4.w;
    }
}

// RAW t = x[N,128] @ W1[128,64] via tf32 mma; result stored fp16.
__global__ __launch_bounds__(256) void k_gemm1(const float* __restrict__ x,
                                               const float* __restrict__ W) {
    __shared__ unsigned xs[128 * 132];
    __shared__ unsigned ws[128 * 72];
    int tid = threadIdx.x;
    int row0 = blockIdx.x * 128;
    const float4* x4 = (const float4*)x;
    const float4* W4 = (const float4*)W;

    #pragma unroll
    for (int i = tid; i < 2048; i += 256) {
        int k = i >> 4, q = i & 15;
        float4 v = W4[i];
        unsigned* p = &ws[k * 72 + q * 4];
        p[0] = f2tf(v.x); p[1] = f2tf(v.y); p[2] = f2tf(v.z); p[3] = f2tf(v.w);
    }
    #pragma unroll
    for (int i = tid; i < 4096; i += 256) {
        int r = i >> 5, q = i & 31;
        int gr = row0 + r;
        float4 v = (gr < NN) ? x4[gr * 32 + q] : make_float4(0, 0, 0, 0);
        unsigned* p = &xs[r * 132 + q * 4];
        p[0] = f2tf(v.x); p[1] = f2tf(v.y); p[2] = f2tf(v.z); p[3] = f2tf(v.w);
    }
    __syncthreads();

    int warp = tid >> 5, lane = tid & 31;
    int gid = lane >> 2, tig = lane & 3;
    int wr = warp * 16;
    float acc[8][4];
    #pragma unroll
    for (int nt = 0; nt < 8; nt++)
        #pragma unroll
        for (int j = 0; j < 4; j++) acc[nt][j] = 0.f;

    #pragma unroll 4
    for (int ks = 0; ks < 16; ks++) {
        int k0 = ks * 8;
        unsigned a[4];
        a[0] = xs[(wr + gid) * 132 + k0 + tig];
        a[1] = xs[(wr + gid + 8) * 132 + k0 + tig];
        a[2] = xs[(wr + gid) * 132 + k0 + tig + 4];
        a[3] = xs[(wr + gid + 8) * 132 + k0 + tig + 4];
        #pragma unroll
        for (int nt = 0; nt < 8; nt++) {
            unsigned b0 = ws[(k0 + tig) * 72 + nt * 8 + gid];
            unsigned b1 = ws[(k0 + tig + 4) * 72 + nt * 8 + gid];
            mma_tf32(acc[nt], a, b0, b1);
        }
    }

    int r0 = row0 + wr + gid;
    int r1 = r0 + 8;
    __half2* t2 = (__half2*)g_t;
    #pragma unroll
    for (int nt = 0; nt < 8; nt++) {
        int c2i = nt * 4 + tig;
        if (r0 < NN) t2[r0 * 32 + c2i] = __floats2half2_rn(acc[nt][0], acc[nt][1]);
        if (r1 < NN) t2[r1 * 32 + c2i] = __floats2half2_rn(acc[nt][2], acc[nt][3]);
    }
}

// CSR gather-reduce over fp16 rows, fp32 accumulate, no atomics.
// 8 threads/node x uint4; 4-way unrolled gather (MLP=4).
template <int LAYER>
__global__ __launch_bounds__(256) void k_aggcsr(const float* __restrict__ b1) {
    int idx = blockIdx.x * 256 + threadIdx.x;
    int d = idx >> 3;
    if (d >= NN) return;
    int sub = idx & 7;
    const uint4* t16 = (const uint4*)(LAYER == 1 ? g_t : g_a);
    int beg = g_off[d], end = g_off[d + 1];
    float s = g_dinv[d];

    float acc[8];
    #pragma unroll
    for (int i = 0; i < 8; i++) acc[i] = 0.f;
    acc8(acc, t16[d * 8 + sub], (LAYER == 1) ? s : 1.f);   // self-loop term

    int j = beg;
    for (; j + 3 < end; j += 4) {
        int s0 = g_srcs[j + 0];
        int s1 = g_srcs[j + 1];
        int s2 = g_srcs[j + 2];
        int s3 = g_srcs[j + 3];
        uint4 u0 = t16[s0 * 8 + sub];
        uint4 u1 = t16[s1 * 8 + sub];
        uint4 u2 = t16[s2 * 8 + sub];
        uint4 u3 = t16[s3 * 8 + sub];
        if (LAYER == 1) {
            acc8(acc, u0, g_dinv[s0]);
            acc8(acc, u1, g_dinv[s1]);
            acc8(acc, u2, g_dinv[s2]);
            acc8(acc, u3, g_dinv[s3]);
        } else {
            acc8(acc, u0, 1.f);
            acc8(acc, u1, 1.f);
            acc8(acc, u2, 1.f);
            acc8(acc, u3, 1.f);
        }
    }
    for (; j < end; j++) {
        int s0 = g_srcs[j];
        uint4 u0 = t16[s0 * 8 + sub];
        acc8(acc, u0, (LAYER == 1) ? g_dinv[s0] : 1.f);
    }

    uint4 o;
    if (LAYER == 1) {
        const float4* b4 = (const float4*)b1;
        float4 ba = b4[sub * 2], bb = b4[sub * 2 + 1];
        float b[8] = {ba.x, ba.y, ba.z, ba.w, bb.x, bb.y, bb.z, bb.w};
        #pragma unroll
        for (int i = 0; i < 8; i++) acc[i] = fmaxf(s * acc[i] + b[i], 0.f) * s;
        *(__half2*)&o.x = __floats2half2_rn(acc[0], acc[1]);
        *(__half2*)&o.y = __floats2half2_rn(acc[2], acc[3]);
        *(__half2*)&o.z = __floats2half2_rn(acc[4], acc[5]);
        *(__half2*)&o.w = __floats2half2_rn(acc[6], acc[7]);
        ((uint4*)g_a)[d * 8 + sub] = o;
    } else {
        #pragma unroll
        for (int i = 0; i < 8; i++) acc[i] *= s;
        *(__half2*)&o.x = __floats2half2_rn(acc[0], acc[1]);
        *(__half2*)&o.y = __floats2half2_rn(acc[2], acc[3]);
        *(__half2*)&o.z = __floats2half2_rn(acc[4], acc[5]);
        *(__half2*)&o.w = __floats2half2_rn(acc[6], acc[7]);
        ((uint4*)g_t)[d * 8 + sub] = o;
    }
}

// out = g_t[N,64](fp16, already dinv-scaled) @ W2[64,128] + b2 via tf32 mma.
__global__ __launch_bounds__(256) void k_gemm2(const float* __restrict__ W2,
                                               const float* __restrict__ b2,
                                               float* __restrict__ out) {
    __shared__ unsigned xs[128 * 68];
    __shared__ unsigned ws[64 * 136];
    int tid = threadIdx.x;
    int row0 = blockIdx.x * 128;
    const uint2* a8 = (const uint2*)g_t;
    const float4* W4 = (const float4*)W2;

    #pragma unroll
    for (int i = tid; i < 2048; i += 256) {
        int k = i >> 5, q = i & 31;
        float4 v = W4[i];
        unsigned* p = &ws[k * 136 + q * 4];
        p[0] = f2tf(v.x); p[1] = f2tf(v.y); p[2] = f2tf(v.z); p[3] = f2tf(v.w);
    }
    #pragma unroll
    for (int i = tid; i < 2048; i += 256) {
        int r = i >> 4, q = i & 15;
        int gr = row0 + r;
        float2 f0 = {0, 0}, f1 = {0, 0};
        if (gr < NN) {
            uint2 u = a8[gr * 16 + q];
            f0 = __half22float2(*(const __half2*)&u.x);
            f1 = __half22float2(*(const __half2*)&u.y);
        }
        unsigned* p = &xs[r * 68 + q * 4];
        p[0] = f2tf(f0.x); p[1] = f2tf(f0.y); p[2] = f2tf(f1.x); p[3] = f2tf(f1.y);
    }
    __syncthreads();

    int warp = tid >> 5, lane = tid & 31;
    int gid = lane >> 2, tig = lane & 3;
    int wr = warp * 16;
    float acc[16][4];
    #pragma unroll
    for (int nt = 0; nt < 16; nt++)
        #pragma unroll
        for (int j = 0; j < 4; j++) acc[nt][j] = 0.f;

    #pragma unroll 2
    for (int ks = 0; ks < 8; ks++) {
        int k0 = ks * 8;
        unsigned a[4];
        a[0] = xs[(wr + gid) * 68 + k0 + tig];
        a[1] = xs[(wr + gid + 8) * 68 + k0 + tig];
        a[2] = xs[(wr + gid) * 68 + k0 + tig + 4];
        a[3] = xs[(wr + gid + 8) * 68 + k0 + tig + 4];
        #pragma unroll
        for (int nt = 0; nt < 16; nt++) {
            unsigned b0 = ws[(k0 + tig) * 136 + nt * 8 + gid];
            unsigned b1 = ws[(k0 + tig + 4) * 136 + nt * 8 + gid];
            mma_tf32(acc[nt], a, b0, b1);
        }
    }

    int r0 = row0 + wr + gid;
    int r1 = r0 + 8;
    float2* o2 = (float2*)out;
    #pragma unroll
    for (int nt = 0; nt < 16; nt++) {
        int col = nt * 8 + 2 * tig;
        float bx = __ldg(&b2[col]), by = __ldg(&b2[col + 1]);
        int c2i = col >> 1;
        if (r0 < NN) o2[r0 * 64 + c2i] = make_float2(acc[nt][0] + bx, acc[nt][1] + by);
        if (r1 < NN) o2[r1 * 64 + c2i] = make_float2(acc[nt][2] + bx, acc[nt][3] + by);
    }
}

extern "C" void kernel_launch(void* const* d_in, const int* in_sizes, int n_in,
                              void* d_out, int out_size) {
    const float* x  = (const float*)d_in[0];
    const int*   ei = (const int*)d_in[1];   // [2, E] int32
    const float* W1 = (const float*)d_in[2];
    const float* b1 = (const float*)d_in[3];
    const float* W2 = (const float*)d_in[4];
    const float* b2 = (const float*)d_in[5];
    float* out = (float*)d_out;

    const int* src = ei;
    const int* dst = ei + NE;

    static cudaStream_t s2 = nullptr;
    static cudaEvent_t e_fork = nullptr, e_join = nullptr;
    if (!s2) {
        cudaStreamCreateWithFlags(&s2, cudaStreamNonBlocking);
        cudaEventCreateWithFlags(&e_fork, cudaEventDisableTiming);
        cudaEventCreateWithFlags(&e_join, cudaEventDisableTiming);
    }

    // Fork: gemm1 runs parallel to CSR build.
    cudaEventRecord(e_fork, 0);
    cudaStreamWaitEvent(s2, e_fork, 0);
    k_gemm1<<<(NN + 127) / 128, 256, 0, s2>>>(x, W1);
    cudaEventRecord(e_join, s2);

    // CSR build: 3 kernels (count -> lookback scan -> fill).
    k_count  <<<(NE / 4 + 255) / 256, 256>>>(dst);
    k_scanall<<<NB_SCAN, 256>>>();
    k_fillcsr<<<(NE / 4 + 255) / 256, 256>>>(src, dst);

    cudaStreamWaitEvent(0, e_join, 0);
    k_aggcsr<1><<<(NN * 8 + 255) / 256, 256>>>(b1);
    k_aggcsr<2><<<(NN * 8 + 255) / 256, 256>>>(b1);
    k_gemm2    <<<(NN + 127) / 128, 256>>>(W2, b2, out);
}